// round 13
// baseline (speedup 1.0000x reference)
#include <cuda_runtime.h>
#include <cuda_fp16.h>
#include <cstdint>

#define KVOL 27
#define CIN  64
#define COUT 64
#define BM   128
#define FEAT_CAP 67108864LL   // halves (128 MiB static image)

__device__ int g_kmap_is64;
// fp16(rna) W image in fragment-pair layout (see prep_B): per k, 4 k-slice
// planes of 256 rows x 4 halves. 27 * 8KB = 216 KB.
__device__ unsigned short g_Bimg[KVOL * CIN * COUT];
// fp16(rna) image of features, rebuilt every launch by prep_feat.
__device__ __half g_feat[FEAT_CAP];

__global__ void detect_kmap_dtype(const unsigned int* __restrict__ km) {
    // int64 little-endian values < 2^31 -> odd 32-bit words all zero.
    // int32 -> odd words are random indices, ~never all zero over 64 samples.
    int all_zero = 1;
    #pragma unroll 1
    for (int i = 0; i < 64; ++i)
        if (km[2 * i + 1] != 0u) { all_zero = 0; break; }
    g_kmap_is64 = all_zero;
}

__global__ void prep_feat(const float* __restrict__ f, long long n) {
    long long i = ((long long)blockIdx.x * blockDim.x + threadIdx.x) * 8;
    if (i + 8 <= n) {
        float4 v0 = *reinterpret_cast<const float4*>(f + i);
        float4 v1 = *reinterpret_cast<const float4*>(f + i + 4);
        __half2 h0 = __floats2half2_rn(v0.x, v0.y);
        __half2 h1 = __floats2half2_rn(v0.z, v0.w);
        __half2 h2 = __floats2half2_rn(v1.x, v1.y);
        __half2 h3 = __floats2half2_rn(v1.z, v1.w);
        uint4 o;
        o.x = *reinterpret_cast<unsigned*>(&h0);
        o.y = *reinterpret_cast<unsigned*>(&h1);
        o.z = *reinterpret_cast<unsigned*>(&h2);
        o.w = *reinterpret_cast<unsigned*>(&h3);
        *reinterpret_cast<uint4*>(&g_feat[i]) = o;
    } else {
        for (; i < n && i < FEAT_CAP; ++i) g_feat[i] = __float2half_rn(f[i]);
    }
}

// Fragment-pair B layout for mma.m16n8k16.row.col fp16 (proven in R11):
//   thread (g=lane>>2, t4=lane&3), col n=co, k-slice ks needs halves
//   { W[16ks+2t4][co], [+1], [+8], [+9] } -> one 8B word at
//   plane ks (2KB), row = co*4 + t4. 16-lane LDS.64 phases are
//   bank-conflict-free (byte stride 8 over consecutive rows).
__global__ void prep_B(const float* __restrict__ wk) {
    const int k = blockIdx.x;
    for (int i = threadIdx.x; i < CIN * COUT; i += blockDim.x) {
        const int ci = i >> 6;
        const int co = i & 63;
        const unsigned short h =
            __half_as_ushort(__float2half_rn(wk[k * 4096 + i]));
        const int ks = ci >> 4;
        const int kk = ci & 15;
        const int t4 = (kk & 7) >> 1;
        const int hi = ((kk >> 3) << 1) | (kk & 1);   // half slot in the word
        g_Bimg[k * 4096 + (ks * 256 + co * 4 + t4) * 4 + hi] = h;
    }
}

__device__ __forceinline__ void mma_f16(float c[4], const uint32_t a[4], const uint32_t b[2]) {
    asm volatile(
        "mma.sync.aligned.m16n8k16.row.col.f32.f16.f16.f32 "
        "{%0,%1,%2,%3}, {%4,%5,%6,%7}, {%8,%9}, {%0,%1,%2,%3};\n"
        : "+f"(c[0]), "+f"(c[1]), "+f"(c[2]), "+f"(c[3])
        : "r"(a[0]), "r"(a[1]), "r"(a[2]), "r"(a[3]),
          "r"(b[0]), "r"(b[1]));
}

__device__ __forceinline__ void ldsm_x4(uint32_t a[4], uint32_t addr) {
    asm volatile("ldmatrix.sync.aligned.m8n8.x4.shared.b16 {%0,%1,%2,%3}, [%4];"
                 : "=r"(a[0]), "=r"(a[1]), "=r"(a[2]), "=r"(a[3]) : "r"(addr));
}

// cp.async 16B, L2-only (gather), zero-fill when sz==0 (masked rows)
__device__ __forceinline__ void cp16_cg_zfill(uint32_t smem, const void* g, int sz) {
    asm volatile("cp.async.cg.shared.global [%0], [%1], 16, %2;\n"
                 :: "r"(smem), "l"(g), "r"(sz) : "memory");
}
// cp.async 16B, L1-cached (weight image: hot across blocks)
__device__ __forceinline__ void cp16_ca(uint32_t smem, const void* g) {
    asm volatile("cp.async.ca.shared.global [%0], [%1], 16;\n"
                 :: "r"(smem), "l"(g) : "memory");
}

extern __shared__ char dyn_smem[];

// SMEM layout (bytes): A stages 4x16KB @0, B stages 4x8KB @65536, sIdx @98304.
#define A_BYTES   16384
#define B_BYTES   8192
#define OFF_B     65536
#define OFF_IDX   98304
#define SMEM_TOTAL (OFF_IDX + BM * KVOL * 4)   // 112,128 B -> 2 CTA/SM

__global__ __launch_bounds__(128, 2)
void sparse_conv_f16(const long long* __restrict__ kmap64,
                     const int* __restrict__ kmap32,
                     const int* __restrict__ kmask,
                     float* __restrict__ out,
                     int n_pts)
{
    int* sIdx = (int*)(dyn_smem + OFF_IDX);
    const uint32_t sbase = (uint32_t)__cvta_generic_to_shared(dyn_smem);

    const int tid  = threadIdx.x;          // 0..127
    const int lane = tid & 31;
    const int warp = tid >> 5;             // 0..3  (M dimension)
    const int m0   = warp * 32;
    const int g    = lane >> 2;            // 0..7
    const int t4   = lane & 3;             // 0..3
    const long long blk0 = (long long)blockIdx.x * BM;
    const int is64 = g_kmap_is64;

    // ---- fused (mask ? idx : -1) for all 128 pts x 27 offsets, coalesced ----
    {
        const long long entry0    = blk0 * KVOL;
        const long long entry_end = (long long)n_pts * KVOL;
        #pragma unroll 1
        for (int j = 0; j < KVOL; ++j) {
            const long long e = entry0 + j * 128 + tid;
            int v = -1;
            if (e < entry_end && kmask[e]) {
                long long idx = is64 ? kmap64[e] : (long long)kmap32[e];
                if (idx < 0 || idx >= n_pts) idx = 0;   // never fault
                v = (int)idx;
            }
            sIdx[j * 128 + tid] = v;
        }
    }
    __syncthreads();

    // gather assignment: 8 lanes cover one 128B fp16 feature row (1 line)
    const int chunk  = tid & 7;            // 16B chunk within row
    const int rowgrp = tid >> 3;           // 0..15

    // fill stage with A gather + B copy for offset k (one cp.async group)
    auto issue = [&](int k, int stage) {
        // B: 8KB copy of the prepped image (4 x 16B per thread)
        const unsigned short* bsrc = g_Bimg + k * 4096;
        const uint32_t bb = sbase + OFF_B + stage * B_BYTES;
        #pragma unroll
        for (int it = 0; it < 4; ++it)
            cp16_ca(bb + it * 2048 + tid * 16, bsrc + it * 1024 + tid * 8);
        // A: 128 rows x 128B, chunk-swizzled (c ^ (row&7)), zfill masked
        const uint32_t ab = sbase + stage * A_BYTES;
        int idxs[8];
        #pragma unroll
        for (int r = 0; r < 8; ++r)
            idxs[r] = sIdx[(r * 16 + rowgrp) * KVOL + k];   // broadcast
        #pragma unroll
        for (int r = 0; r < 8; ++r) {
            const int row = r * 16 + rowgrp;
            const int v   = idxs[r];
            const long long i = (v >= 0) ? (long long)v : 0;
            cp16_cg_zfill(ab + row * 128 + ((chunk ^ (row & 7)) << 4),
                          g_feat + i * CIN + chunk * 8, (v >= 0) ? 16 : 0);
        }
        asm volatile("cp.async.commit_group;\n" ::: "memory");
    };

    float acc[2][8][4];
    #pragma unroll
    for (int mi = 0; mi < 2; ++mi)
        #pragma unroll
        for (int ni = 0; ni < 8; ++ni)
            #pragma unroll
            for (int j = 0; j < 4; ++j)
                acc[mi][ni][j] = 0.0f;

    issue(0, 0);
    issue(1, 1);
    issue(2, 2);   // prefetch depth 3

    // ldmatrix lane addressing (row-major A, 16B chunk swizzle c^(row&7))
    const int ldrow  = (lane & 7) + 8 * ((lane >> 3) & 1);
    const int ldcoff = lane >> 4;                   // 0 or 1
    const int brow   = g * 4 + t4;                  // B row base (ni=0)

    #pragma unroll 1
    for (int k = 0; k < KVOL; ++k) {
        // group k complete; allow the (up to 2) newer groups to stay in flight
        if (k <= KVOL - 3) {
            asm volatile("cp.async.wait_group 2;\n" ::: "memory");
        } else if (k == KVOL - 2) {
            asm volatile("cp.async.wait_group 1;\n" ::: "memory");
        } else {
            asm volatile("cp.async.wait_group 0;\n" ::: "memory");
        }
        // One sync per k: admits stage k to all warps AND retires compute(k-1),
        // so refilling stage (k+3)&3 == (k-1)&3 below is safe.
        __syncthreads();

        if (k + 3 < KVOL) issue(k + 3, (k + 3) & 3);

        const int      st   = k & 3;
        const uint32_t a_sm = sbase + st * A_BYTES;
        const char*    Bp   = dyn_smem + OFF_B + st * B_BYTES;

        // ---- warp tile 32(M) x 64(N), K=64 in 4 slices of 16 ----
        #pragma unroll
        for (int ks = 0; ks < 4; ++ks) {
            uint32_t b[8][2];
            #pragma unroll
            for (int ni = 0; ni < 8; ++ni) {
                const uint2 pv = *reinterpret_cast<const uint2*>(
                    Bp + ks * 2048 + (ni * 32 + brow) * 8);
                b[ni][0] = pv.x;
                b[ni][1] = pv.y;
            }
            uint32_t a[2][4];
            #pragma unroll
            for (int mi = 0; mi < 2; ++mi) {
                const int row = m0 + mi * 16 + ldrow;
                ldsm_x4(a[mi], a_sm + row * 128 +
                               (((2 * ks + ldcoff) ^ (row & 7)) << 4));
            }
            #pragma unroll
            for (int mi = 0; mi < 2; ++mi)
                #pragma unroll
                for (int ni = 0; ni < 8; ++ni)
                    mma_f16(acc[mi][ni], a[mi], b[ni]);
        }
    }

    // ---- epilogue: c frag layout -> out[n, co] (fp32) ----
    #pragma unroll
    for (int mi = 0; mi < 2; ++mi) {
        const long long r0 = blk0 + m0 + mi * 16 + g;
        #pragma unroll
        for (int ni = 0; ni < 8; ++ni) {
            const int col = ni * 8 + t4 * 2;
            if (r0 < n_pts)
                *reinterpret_cast<float2*>(out + r0 * COUT + col) =
                    make_float2(acc[mi][ni][0], acc[mi][ni][1]);
            if (r0 + 8 < n_pts)
                *reinterpret_cast<float2*>(out + (r0 + 8) * COUT + col) =
                    make_float2(acc[mi][ni][2], acc[mi][ni][3]);
        }
    }
}

extern "C" void kernel_launch(void* const* d_in, const int* in_sizes, int n_in,
                              void* d_out, int out_size) {
    const float* features = (const float*)d_in[0];
    const float* wkernel  = (const float*)d_in[1];
    const void*  kmap     = d_in[2];
    const int*   kmask    = (const int*)d_in[3];
    float*       out      = (float*)d_out;

    long long nfeat = (long long)in_sizes[0];
    if (nfeat > FEAT_CAP) nfeat = FEAT_CAP;          // defensive
    int n_pts = (int)(nfeat / CIN);
    const int grid = (n_pts + BM - 1) / BM;

    cudaFuncSetAttribute(sparse_conv_f16,
                         cudaFuncAttributeMaxDynamicSharedMemorySize, SMEM_TOTAL);

    detect_kmap_dtype<<<1, 1>>>((const unsigned int*)kmap);
    prep_feat<<<(int)((nfeat / 8 + 255) / 256), 256>>>(features, nfeat);
    prep_B<<<KVOL, 128>>>(wkernel);
    sparse_conv_f16<<<grid, 128, SMEM_TOTAL>>>((const long long*)kmap,
                                               (const int*)kmap,
                                               kmask, out, n_pts);
}

// round 14
// speedup vs baseline: 1.4840x; 1.4840x over previous
#include <cuda_runtime.h>
#include <cuda_fp16.h>
#include <cstdint>

#define KVOL 27
#define CIN  64
#define COUT 64
#define BM   256
#define NTHR 256
#define FEAT_CAP 67108864LL   // halves (128 MiB static image)

__device__ int g_kmap_is64;
// fp16(rna) W image in fragment-pair layout (see prep_B): per k, 4 k-slice
// planes of 256 rows x 4 halves. 27 * 8KB = 216 KB.
__device__ unsigned short g_Bimg[KVOL * CIN * COUT];
// fp16(rna) image of features, rebuilt every launch by prep_feat.
__device__ __half g_feat[FEAT_CAP];

__global__ void detect_kmap_dtype(const unsigned int* __restrict__ km) {
    // int64 little-endian values < 2^31 -> odd 32-bit words all zero.
    // int32 -> odd words are random indices, ~never all zero over 64 samples.
    int all_zero = 1;
    #pragma unroll 1
    for (int i = 0; i < 64; ++i)
        if (km[2 * i + 1] != 0u) { all_zero = 0; break; }
    g_kmap_is64 = all_zero;
}

__global__ void prep_feat(const float* __restrict__ f, long long n) {
    long long i = ((long long)blockIdx.x * blockDim.x + threadIdx.x) * 8;
    if (i + 8 <= n) {
        float4 v0 = *reinterpret_cast<const float4*>(f + i);
        float4 v1 = *reinterpret_cast<const float4*>(f + i + 4);
        __half2 h0 = __floats2half2_rn(v0.x, v0.y);
        __half2 h1 = __floats2half2_rn(v0.z, v0.w);
        __half2 h2 = __floats2half2_rn(v1.x, v1.y);
        __half2 h3 = __floats2half2_rn(v1.z, v1.w);
        uint4 o;
        o.x = *reinterpret_cast<unsigned*>(&h0);
        o.y = *reinterpret_cast<unsigned*>(&h1);
        o.z = *reinterpret_cast<unsigned*>(&h2);
        o.w = *reinterpret_cast<unsigned*>(&h3);
        *reinterpret_cast<uint4*>(&g_feat[i]) = o;
    } else {
        for (; i < n && i < FEAT_CAP; ++i) g_feat[i] = __float2half_rn(f[i]);
    }
}

// Fragment-pair B layout for mma.m16n8k16.row.col fp16 (proven in R11):
//   thread (g=lane>>2, t4=lane&3), col n=co, k-slice ks needs halves
//   { W[16ks+2t4][co], [+1], [+8], [+9] } -> one 8B word at
//   plane ks (2KB), row = co*4 + t4. 16-lane LDS.64 phases are
//   bank-conflict-free (byte stride 8 over consecutive rows).
__global__ void prep_B(const float* __restrict__ wk) {
    const int k = blockIdx.x;
    for (int i = threadIdx.x; i < CIN * COUT; i += blockDim.x) {
        const int ci = i >> 6;
        const int co = i & 63;
        const unsigned short h =
            __half_as_ushort(__float2half_rn(wk[k * 4096 + i]));
        const int ks = ci >> 4;
        const int kk = ci & 15;
        const int t4 = (kk & 7) >> 1;
        const int hi = ((kk >> 3) << 1) | (kk & 1);   // half slot in the word
        g_Bimg[k * 4096 + (ks * 256 + co * 4 + t4) * 4 + hi] = h;
    }
}

__device__ __forceinline__ void mma_f16(float c[4], const uint32_t a[4], const uint32_t b[2]) {
    asm volatile(
        "mma.sync.aligned.m16n8k16.row.col.f32.f16.f16.f32 "
        "{%0,%1,%2,%3}, {%4,%5,%6,%7}, {%8,%9}, {%0,%1,%2,%3};\n"
        : "+f"(c[0]), "+f"(c[1]), "+f"(c[2]), "+f"(c[3])
        : "r"(a[0]), "r"(a[1]), "r"(a[2]), "r"(a[3]),
          "r"(b[0]), "r"(b[1]));
}

__device__ __forceinline__ void ldsm_x4(uint32_t a[4], uint32_t addr) {
    asm volatile("ldmatrix.sync.aligned.m8n8.x4.shared.b16 {%0,%1,%2,%3}, [%4];"
                 : "=r"(a[0]), "=r"(a[1]), "=r"(a[2]), "=r"(a[3]) : "r"(addr));
}

// cp.async 16B, L2-only (gather), zero-fill when sz==0 (masked rows)
__device__ __forceinline__ void cp16_cg_zfill(uint32_t smem, const void* g, int sz) {
    asm volatile("cp.async.cg.shared.global [%0], [%1], 16, %2;\n"
                 :: "r"(smem), "l"(g), "r"(sz) : "memory");
}
// cp.async 16B, L1-cached (weight image: hot across blocks)
__device__ __forceinline__ void cp16_ca(uint32_t smem, const void* g) {
    asm volatile("cp.async.ca.shared.global [%0], [%1], 16;\n"
                 :: "r"(smem), "l"(g) : "memory");
}

extern __shared__ char dyn_smem[];

// SMEM layout (bytes): A stages 2x32KB @0, B stages 2x8KB @65536, sIdx @81920.
#define A_BYTES   32768
#define B_BYTES   8192
#define OFF_B     65536
#define OFF_IDX   81920
#define SMEM_TOTAL (OFF_IDX + BM * KVOL * 4)   // 109,568 B -> 2 CTA/SM (16 warps)

__global__ __launch_bounds__(NTHR, 2)
void sparse_conv_f16(const long long* __restrict__ kmap64,
                     const int* __restrict__ kmap32,
                     const int* __restrict__ kmask,
                     float* __restrict__ out,
                     int n_pts)
{
    int* sIdx = (int*)(dyn_smem + OFF_IDX);
    const uint32_t sbase = (uint32_t)__cvta_generic_to_shared(dyn_smem);

    const int tid  = threadIdx.x;          // 0..255
    const int lane = tid & 31;
    const int warp = tid >> 5;             // 0..7  (M dimension)
    const int m0   = warp * 32;
    const int g    = lane >> 2;            // 0..7
    const int t4   = lane & 3;             // 0..3
    const long long blk0 = (long long)blockIdx.x * BM;
    const int is64 = g_kmap_is64;

    // ---- fused (mask ? idx : -1) for all 256 pts x 27 offsets, coalesced ----
    {
        const long long entry0    = blk0 * KVOL;
        const long long entry_end = (long long)n_pts * KVOL;
        #pragma unroll 1
        for (int j = 0; j < KVOL; ++j) {
            const long long e = entry0 + j * NTHR + tid;
            int v = -1;
            if (e < entry_end && kmask[e]) {
                long long idx = is64 ? kmap64[e] : (long long)kmap32[e];
                if (idx < 0 || idx >= n_pts) idx = 0;   // never fault
                v = (int)idx;
            }
            sIdx[j * BM + tid] = v;
        }
    }
    __syncthreads();

    // gather assignment: 8 lanes cover one 128B fp16 feature row (1 line)
    const int chunk  = tid & 7;            // 16B chunk within row
    const int rowgrp = tid >> 3;           // 0..31

    // fill stage with A gather + B copy for offset k (one cp.async group)
    auto issue = [&](int k, int stage) {
        // B: 8KB copy of the prepped image (2 x 16B per thread)
        const unsigned short* bsrc = g_Bimg + k * 4096;
        const uint32_t bb = sbase + OFF_B + stage * B_BYTES;
        #pragma unroll
        for (int it = 0; it < 2; ++it)
            cp16_ca(bb + it * 4096 + tid * 16, bsrc + it * 2048 + tid * 8);
        // A: 256 rows x 128B, chunk-swizzled (c ^ (row&7)), zfill masked
        const uint32_t ab = sbase + stage * A_BYTES;
        int idxs[8];
        #pragma unroll
        for (int r = 0; r < 8; ++r)
            idxs[r] = sIdx[(r * 32 + rowgrp) * KVOL + k];   // broadcast
        #pragma unroll
        for (int r = 0; r < 8; ++r) {
            const int row = r * 32 + rowgrp;
            const int v   = idxs[r];
            const long long i = (v >= 0) ? (long long)v : 0;
            cp16_cg_zfill(ab + row * 128 + ((chunk ^ (row & 7)) << 4),
                          g_feat + i * CIN + chunk * 8, (v >= 0) ? 16 : 0);
        }
        asm volatile("cp.async.commit_group;\n" ::: "memory");
    };

    float acc[2][8][4];
    #pragma unroll
    for (int mi = 0; mi < 2; ++mi)
        #pragma unroll
        for (int ni = 0; ni < 8; ++ni)
            #pragma unroll
            for (int j = 0; j < 4; ++j)
                acc[mi][ni][j] = 0.0f;

    issue(0, 0);   // prologue

    // ldmatrix lane addressing (row-major A, 16B chunk swizzle c^(row&7))
    const int ldrow  = (lane & 7) + 8 * ((lane >> 3) & 1);
    const int ldcoff = lane >> 4;                   // 0 or 1
    const int brow   = g * 4 + t4;                  // B row base (ni=0)

    #pragma unroll 1
    for (int k = 0; k < KVOL; ++k) {
        const int cur = k & 1;
        if (k + 1 < KVOL) {
            issue(k + 1, cur ^ 1);                           // overlap with mma(k)
            asm volatile("cp.async.wait_group 1;\n" ::: "memory");
        } else {
            asm volatile("cp.async.wait_group 0;\n" ::: "memory");
        }
        __syncthreads();   // buffer `cur` complete across all threads

        const uint32_t a_sm = sbase + cur * A_BYTES;
        const char*    Bp   = dyn_smem + OFF_B + cur * B_BYTES;

        // ---- warp tile 32(M) x 64(N), K=64 in 4 slices of 16 ----
        #pragma unroll
        for (int ks = 0; ks < 4; ++ks) {
            uint32_t b[8][2];
            #pragma unroll
            for (int ni = 0; ni < 8; ++ni) {
                const uint2 pv = *reinterpret_cast<const uint2*>(
                    Bp + ks * 2048 + (ni * 32 + brow) * 8);
                b[ni][0] = pv.x;
                b[ni][1] = pv.y;
            }
            uint32_t a[2][4];
            #pragma unroll
            for (int mi = 0; mi < 2; ++mi) {
                const int row = m0 + mi * 16 + ldrow;
                ldsm_x4(a[mi], a_sm + row * 128 +
                               (((2 * ks + ldcoff) ^ (row & 7)) << 4));
            }
            #pragma unroll
            for (int mi = 0; mi < 2; ++mi)
                #pragma unroll
                for (int ni = 0; ni < 8; ++ni)
                    mma_f16(acc[mi][ni], a[mi], b[ni]);
        }
        __syncthreads();   // protect `cur` before it is re-issued at k+2
    }

    // ---- epilogue: c frag layout -> out[n, co] (fp32) ----
    #pragma unroll
    for (int mi = 0; mi < 2; ++mi) {
        const long long r0 = blk0 + m0 + mi * 16 + g;
        #pragma unroll
        for (int ni = 0; ni < 8; ++ni) {
            const int col = ni * 8 + t4 * 2;
            if (r0 < n_pts)
                *reinterpret_cast<float2*>(out + r0 * COUT + col) =
                    make_float2(acc[mi][ni][0], acc[mi][ni][1]);
            if (r0 + 8 < n_pts)
                *reinterpret_cast<float2*>(out + (r0 + 8) * COUT + col) =
                    make_float2(acc[mi][ni][2], acc[mi][ni][3]);
        }
    }
}

extern "C" void kernel_launch(void* const* d_in, const int* in_sizes, int n_in,
                              void* d_out, int out_size) {
    const float* features = (const float*)d_in[0];
    const float* wkernel  = (const float*)d_in[1];
    const void*  kmap     = d_in[2];
    const int*   kmask    = (const int*)d_in[3];
    float*       out      = (float*)d_out;

    long long nfeat = (long long)in_sizes[0];
    if (nfeat > FEAT_CAP) nfeat = FEAT_CAP;          // defensive
    int n_pts = (int)(nfeat / CIN);
    const int grid = (n_pts + BM - 1) / BM;

    cudaFuncSetAttribute(sparse_conv_f16,
                         cudaFuncAttributeMaxDynamicSharedMemorySize, SMEM_TOTAL);

    detect_kmap_dtype<<<1, 1>>>((const unsigned int*)kmap);
    prep_feat<<<(int)((nfeat / 8 + 255) / 256), 256>>>(features, nfeat);
    prep_B<<<KVOL, 128>>>(wkernel);
    sparse_conv_f16<<<grid, NTHR, SMEM_TOTAL>>>((const long long*)kmap,
                                                (const int*)kmap,
                                                kmask, out, n_pts);
}